// round 2
// baseline (speedup 1.0000x reference)
#include <cuda_runtime.h>
#include <cstdint>

#define HID 16
#define NT 400000
#define ND 200000
#define NDEV 8
#define TSTRIDE 44   // tasks agg row: [dt 0..4 (pad to 8) | devt 8..19 | tt_to 20..31 | tt_from 32..43]
#define DSTRIDE 24   // data agg row:  [td 0..11 | devd 12..23]

// ---------------- scratch (static device allocations) ----------------
__device__ __align__(16) float g_agg_tasks[(size_t)NT * TSTRIDE];   // 70.4 MB
__device__ __align__(16) float g_agg_data [(size_t)ND * DSTRIDE];   // 19.2 MB
__device__ __align__(16) float g_agg_tdev [NDEV * 12];
__device__ __align__(16) float g_agg_ddev [NDEV * 8];

__device__ __forceinline__ void red4(float* p, float a, float b, float c, float d) {
    asm volatile("red.global.add.v4.f32 [%0], {%1,%2,%3,%4};"
                 :: "l"(p), "f"(a), "f"(b), "f"(c), "f"(d) : "memory");
}
__device__ __forceinline__ void red1(float* p, float a) {
    asm volatile("red.global.add.f32 [%0], %1;" :: "l"(p), "f"(a) : "memory");
}

__device__ __forceinline__ float* agg_sel(int which) {
    return (which == 0) ? g_agg_tasks : g_agg_data;
}

// ---------------- zero scratch ----------------
__global__ void zero_all() {
    size_t i  = (size_t)blockIdx.x * blockDim.x + threadIdx.x;
    size_t st = (size_t)gridDim.x * blockDim.x;
    float4 z = make_float4(0.f, 0.f, 0.f, 0.f);
    size_t n1 = (size_t)NT * TSTRIDE / 4;
    for (size_t j = i; j < n1; j += st) ((float4*)g_agg_tasks)[j] = z;
    size_t n2 = (size_t)ND * DSTRIDE / 4;
    for (size_t j = i; j < n2; j += st) ((float4*)g_agg_data)[j] = z;
    if (i < NDEV * 12) g_agg_tdev[i] = 0.f;
    if (i < NDEV * 8)  g_agg_ddev[i] = 0.f;
}

// ---------------- edge scatter: 12-dim src features ----------------
__global__ void scatter12(const float* __restrict__ xsrc, const int* __restrict__ ei,
                          int E, int which, int offset, int stride) {
    int e = blockIdx.x * blockDim.x + threadIdx.x;
    if (e >= E) return;
    int s = ei[e];
    int d = ei[E + e];
    const float4* xr = (const float4*)(xsrc + (size_t)s * 12);
    float4 a = xr[0], b = xr[1], c = xr[2];
    float* p = agg_sel(which) + (size_t)d * stride + offset;
    red4(p,     a.x, a.y, a.z, a.w);
    red4(p + 4, b.x, b.y, b.z, b.w);
    red4(p + 8, c.x, c.y, c.z, c.w);
}

// ---------------- edge scatter: 5-dim src features ----------------
__global__ void scatter5(const float* __restrict__ xsrc, const int* __restrict__ ei,
                         int E, int which, int offset, int stride) {
    int e = blockIdx.x * blockDim.x + threadIdx.x;
    if (e >= E) return;
    int s = ei[e];
    int d = ei[E + e];
    const float* xr = xsrc + (size_t)s * 5;
    float v0 = xr[0], v1 = xr[1], v2 = xr[2], v3 = xr[3], v4 = xr[4];
    float* p = agg_sel(which) + (size_t)d * stride + offset;
    red4(p, v0, v1, v2, v3);
    red1(p + 4, v4);
}

// ---------------- edge scatter into device nodes (dst in [0,8)) ----------------
template <int D>
__global__ void scatter_dev(const float* __restrict__ xsrc, const int* __restrict__ ei,
                            int E, int which) {
    __shared__ float acc[NDEV * D];
    for (int i = threadIdx.x; i < NDEV * D; i += blockDim.x) acc[i] = 0.f;
    __syncthreads();
    for (int e = blockIdx.x * blockDim.x + threadIdx.x; e < E;
         e += gridDim.x * blockDim.x) {
        int s = ei[e];
        int d = ei[E + e];
        const float* xr = xsrc + (size_t)s * D;
#pragma unroll
        for (int k = 0; k < D; k++) atomicAdd(&acc[d * D + k], xr[k]);
    }
    __syncthreads();
    float* agg = (which == 2) ? g_agg_tdev : g_agg_ddev;
    for (int i = threadIdx.x; i < NDEV * D; i += blockDim.x)
        if (acc[i] != 0.f) red1(&agg[i], acc[i]);
}

// ---------------- dense per-node helpers ----------------
__device__ __forceinline__ void mad16(float* acc, float v, const float* w) {
#pragma unroll
    for (int q = 0; q < 4; q++) {
        float4 ww = ((const float4*)w)[q];
        acc[q * 4 + 0] += v * ww.x;
        acc[q * 4 + 1] += v * ww.y;
        acc[q * 4 + 2] += v * ww.z;
        acc[q * 4 + 3] += v * ww.w;
    }
}

__device__ __forceinline__ void ln_act_store(float* acc, const float* gam, const float* bet,
                                             float* outp) {
    float mu = 0.f;
#pragma unroll
    for (int h = 0; h < 16; h++) mu += acc[h];
    mu *= (1.f / 16.f);
    float var = 0.f;
#pragma unroll
    for (int h = 0; h < 16; h++) { float z = acc[h] - mu; var += z * z; }
    var *= (1.f / 16.f);
    float inv = rsqrtf(var + 1e-5f);
    float4 o[4];
    float* of = (float*)o;
#pragma unroll
    for (int h = 0; h < 16; h++) {
        float y = (acc[h] - mu) * inv * gam[h] + bet[h];
        of[h] = (y > 0.f) ? y : 0.01f * y;
    }
    float4* op = (float4*)outp;
#pragma unroll
    for (int q = 0; q < 4; q++) op[q] = o[q];
}

// ---------------- tasks node pass ----------------
__global__ void tasks_node(const float* __restrict__ x_tasks,
                           const float* __restrict__ W_rel5, const float* __restrict__ W_rel12,
                           const float* __restrict__ b_rel, const float* __restrict__ W_root12,
                           const float* __restrict__ ln_g, const float* __restrict__ ln_b,
                           float* __restrict__ out) {
    __shared__ __align__(16) float W5[80], Wdevt[192], Wto[192], Wfrom[192], Wroot[192];
    __shared__ float bias[16], gam[16], bet[16];
    int t = threadIdx.x;
    if (t < 80) W5[t] = W_rel5[t];              // W_rel5[0]
    if (t < 192) {
        Wdevt[t] = W_rel12[2 * 192 + t];
        Wto[t]   = W_rel12[4 * 192 + t];
        Wfrom[t] = W_rel12[5 * 192 + t];
        Wroot[t] = W_root12[t] + W_root12[2 * 192 + t] + W_root12[4 * 192 + t] +
                   W_root12[5 * 192 + t];
    }
    if (t < 16) {
        bias[t] = b_rel[t] + b_rel[3 * 16 + t] + b_rel[6 * 16 + t] + b_rel[7 * 16 + t];
        gam[t] = ln_g[t];
        bet[t] = ln_b[t];
    }
    __syncthreads();
    int n = blockIdx.x * blockDim.x + t;
    if (n >= NT) return;

    float acc[16];
#pragma unroll
    for (int h = 0; h < 16; h++) acc[h] = bias[h];

    const float4* row = (const float4*)(g_agg_tasks + (size_t)n * TSTRIDE);
    float4 r[11];
#pragma unroll
    for (int q = 0; q < 11; q++) r[q] = row[q];
    const float* rf = (const float*)r;

#pragma unroll
    for (int d = 0; d < 5; d++)  mad16(acc, rf[d],      &W5[d * 16]);
#pragma unroll
    for (int d = 0; d < 12; d++) mad16(acc, rf[8 + d],  &Wdevt[d * 16]);
#pragma unroll
    for (int d = 0; d < 12; d++) mad16(acc, rf[20 + d], &Wto[d * 16]);
#pragma unroll
    for (int d = 0; d < 12; d++) mad16(acc, rf[32 + d], &Wfrom[d * 16]);

    const float4* xt = (const float4*)(x_tasks + (size_t)n * 12);
    float4 xv[3];
#pragma unroll
    for (int q = 0; q < 3; q++) xv[q] = xt[q];
    const float* xf = (const float*)xv;
#pragma unroll
    for (int d = 0; d < 12; d++) mad16(acc, xf[d], &Wroot[d * 16]);

    ln_act_store(acc, gam, bet, out + (size_t)n * 16);
}

// ---------------- data node pass ----------------
__global__ void data_node(const float* __restrict__ x_data,
                          const float* __restrict__ W_rel12, const float* __restrict__ b_rel,
                          const float* __restrict__ W_root5,
                          const float* __restrict__ ln_g, const float* __restrict__ ln_b,
                          float* __restrict__ out) {
    __shared__ __align__(16) float Wtd[192], Wdevd[192], Wroot[80];
    __shared__ float bias[16], gam[16], bet[16];
    int t = threadIdx.x;
    if (t < 192) { Wtd[t] = W_rel12[t]; Wdevd[t] = W_rel12[3 * 192 + t]; }
    if (t < 80)  Wroot[t] = W_root5[t] + W_root5[80 + t];
    if (t < 16) {
        bias[t] = b_rel[16 + t] + b_rel[5 * 16 + t];
        gam[t] = ln_g[16 + t];
        bet[t] = ln_b[16 + t];
    }
    __syncthreads();
    int n = blockIdx.x * blockDim.x + t;
    if (n >= ND) return;

    float acc[16];
#pragma unroll
    for (int h = 0; h < 16; h++) acc[h] = bias[h];

    const float4* row = (const float4*)(g_agg_data + (size_t)n * DSTRIDE);
    float4 r[6];
#pragma unroll
    for (int q = 0; q < 6; q++) r[q] = row[q];
    const float* rf = (const float*)r;

#pragma unroll
    for (int d = 0; d < 12; d++) mad16(acc, rf[d],      &Wtd[d * 16]);
#pragma unroll
    for (int d = 0; d < 12; d++) mad16(acc, rf[12 + d], &Wdevd[d * 16]);

    const float* xd = x_data + (size_t)n * 5;
#pragma unroll
    for (int d = 0; d < 5; d++)  mad16(acc, xd[d], &Wroot[d * 16]);

    ln_act_store(acc, gam, bet, out + (size_t)n * 16);
}

// ---------------- devices node pass (8 nodes, trivial) ----------------
__global__ void dev_node(const float* __restrict__ x_dev,
                         const float* __restrict__ W_rel5, const float* __restrict__ W_rel12,
                         const float* __restrict__ b_rel, const float* __restrict__ W_root12,
                         const float* __restrict__ ln_g, const float* __restrict__ ln_b,
                         float* __restrict__ out) {
    int n = threadIdx.x;
    if (n >= NDEV) return;
    float acc[16];
#pragma unroll
    for (int h = 0; h < 16; h++) acc[h] = b_rel[2 * 16 + h] + b_rel[4 * 16 + h];
    for (int d = 0; d < 12; d++) {
        float v = g_agg_tdev[n * 12 + d];
#pragma unroll
        for (int h = 0; h < 16; h++) acc[h] += v * W_rel12[1 * 192 + d * 16 + h];
    }
    for (int d = 0; d < 5; d++) {
        float v = g_agg_ddev[n * 5 + d];
#pragma unroll
        for (int h = 0; h < 16; h++) acc[h] += v * W_rel5[80 + d * 16 + h];
    }
    for (int d = 0; d < 12; d++) {
        float v = x_dev[n * 12 + d];
#pragma unroll
        for (int h = 0; h < 16; h++)
            acc[h] += v * (W_root12[1 * 192 + d * 16 + h] + W_root12[3 * 192 + d * 16 + h]);
    }
    float gam[16], bet[16];
#pragma unroll
    for (int h = 0; h < 16; h++) { gam[h] = ln_g[2 * 16 + h]; bet[h] = ln_b[2 * 16 + h]; }
    ln_act_store(acc, gam, bet, out + (size_t)n * 16);
}

// ---------------- launch ----------------
extern "C" void kernel_launch(void* const* d_in, const int* in_sizes, int n_in,
                              void* d_out, int out_size) {
    const float* x_tasks = (const float*)d_in[0];
    const float* x_data  = (const float*)d_in[1];
    const float* x_dev   = (const float*)d_in[2];
    const int* ei_dt   = (const int*)d_in[3];   // data  -> tasks
    const int* ei_td   = (const int*)d_in[4];   // tasks -> data
    const int* ei_tdev = (const int*)d_in[5];   // tasks -> devices
    const int* ei_devt = (const int*)d_in[6];   // devices -> tasks
    const int* ei_ddev = (const int*)d_in[7];   // data  -> devices
    const int* ei_devd = (const int*)d_in[8];   // devices -> data
    const int* ei_tto  = (const int*)d_in[9];   // tasks -> tasks (to)
    const int* ei_ttf  = (const int*)d_in[10];  // tasks -> tasks (from)
    const float* W_rel5   = (const float*)d_in[11];
    const float* W_rel12  = (const float*)d_in[12];
    const float* b_rel    = (const float*)d_in[13];
    const float* W_root5  = (const float*)d_in[14];
    const float* W_root12 = (const float*)d_in[15];
    const float* ln_g     = (const float*)d_in[16];
    const float* ln_b     = (const float*)d_in[17];
    float* out = (float*)d_out;

    int E_dt   = in_sizes[3]  / 2;
    int E_td   = in_sizes[4]  / 2;
    int E_tdev = in_sizes[5]  / 2;
    int E_devt = in_sizes[6]  / 2;
    int E_ddev = in_sizes[7]  / 2;
    int E_devd = in_sizes[8]  / 2;
    int E_tto  = in_sizes[9]  / 2;
    int E_ttf  = in_sizes[10] / 2;

    const int TB = 256;
    zero_all<<<2048, TB>>>();

    // scatter into tasks agg
    scatter5 <<<(E_dt   + TB - 1) / TB, TB>>>(x_data,  ei_dt,   E_dt,   0, 0,  TSTRIDE);
    scatter12<<<(E_devt + TB - 1) / TB, TB>>>(x_dev,   ei_devt, E_devt, 0, 8,  TSTRIDE);
    scatter12<<<(E_tto  + TB - 1) / TB, TB>>>(x_tasks, ei_tto,  E_tto,  0, 20, TSTRIDE);
    scatter12<<<(E_ttf  + TB - 1) / TB, TB>>>(x_tasks, ei_ttf,  E_ttf,  0, 32, TSTRIDE);
    // scatter into data agg
    scatter12<<<(E_td   + TB - 1) / TB, TB>>>(x_tasks, ei_td,   E_td,   1, 0,  DSTRIDE);
    scatter12<<<(E_devd + TB - 1) / TB, TB>>>(x_dev,   ei_devd, E_devd, 1, 12, DSTRIDE);
    // scatter into device nodes (shared-mem accumulate)
    scatter_dev<12><<<256, TB>>>(x_tasks, ei_tdev, E_tdev, 2);
    scatter_dev<5> <<<256, TB>>>(x_data,  ei_ddev, E_ddev, 3);

    // node passes
    tasks_node<<<(NT + TB - 1) / TB, TB>>>(x_tasks, W_rel5, W_rel12, b_rel, W_root12,
                                           ln_g, ln_b, out);
    data_node <<<(ND + TB - 1) / TB, TB>>>(x_data, W_rel12, b_rel, W_root5,
                                           ln_g, ln_b, out + (size_t)NT * HID);
    dev_node  <<<1, 32>>>(x_dev, W_rel5, W_rel12, b_rel, W_root12,
                          ln_g, ln_b, out + (size_t)(NT + ND) * HID);
}